// round 3
// baseline (speedup 1.0000x reference)
#include <cuda_runtime.h>

// ---------------- problem constants ----------------
#define T_STEPS 300
#define NB 4
#define MSL 1200            // T_STEPS * NB time-batch slices

// psp recursion constants (double-computed, rounded to f32 by compiler)
#define A_SR 0.90483741803595952f   // exp(-1/10)
#define A_RF 0.36787944117144233f   // exp(-1)
#define C_SR 0.27182818284590452f   // e/10
#define C_RF -54.365636569180904f   // -2*10*e
#define THETA 10.0f

// ---------------- scratch buffers (time-major [t][n][c][h][w]) ----------------
__device__ float g_buf1[2457600];   // pooled1 / x1 : [1200][2][32][32]
__device__ float g_buf2[39321600];  // conv1   / x2 : [1200][32][32][32]
__device__ float g_buf3[9830400];   // pool3   / x3 : [1200][32][16][16]
__device__ float g_buf4[19660800];  // conv2   / x4 : [1200][64][16][16]
__device__ float g_buf5[4915200];   // pool5   / x5 : [1200][64][8][8]
__device__ float g_buf6[4915200];   // conv3   / x6 : [1200][64][8][8]
__device__ float g_buf7[307200];    // fc1     / x7 : [1200][256]
__device__ float g_buf8[13200];     // fc2          : [1200][11]

// ---------------- 4x4 sum pool + transpose NCHWT -> [t][n][c][h][w] ----------------
__global__ void k_pool4(const float* __restrict__ s_in, float* __restrict__ y) {
    int i = blockIdx.x * blockDim.x + threadIdx.x;
    if (i >= 2457600) return;
    int t = i % 300;
    int s = i / 300;                 // s = (((n*2+c)*32+h)*32+w), t fastest -> coalesced reads
    int w = s & 31, h = (s >> 5) & 31, c = (s >> 10) & 1, n = s >> 11;
    const float* base = s_in + ((((n * 2 + c) * 128 + h * 4) * 128) + w * 4) * 300 + t;
    float acc = 0.f;
#pragma unroll
    for (int di = 0; di < 4; di++)
#pragma unroll
        for (int dj = 0; dj < 4; dj++)
            acc += base[(di * 128 + dj) * 300];
    y[(((t * 4 + n) * 2 + c) * 32 + h) * 32 + w] = 11.0f * acc;
}

// ---------------- generic 2x2 sum pool (time-major) ----------------
__global__ void k_pool2(const float* __restrict__ x, float* __restrict__ y,
                        int C, int Ho, int Wo, int total) {
    int i = blockIdx.x * blockDim.x + threadIdx.x;
    if (i >= total) return;
    int w = i % Wo;
    int h = (i / Wo) % Ho;
    int c = (i / (Wo * Ho)) % C;
    int m = i / (Wo * Ho * C);
    const float* b = x + ((m * C + c) * (2 * Ho) + 2 * h) * (2 * Wo) + 2 * w;
    int rs = 2 * Wo;
    y[i] = 11.0f * (b[0] + b[1] + b[rs] + b[rs + 1]);
}

// ---------------- psp + spike, in-place on [t][nn] layout ----------------
__global__ void k_psp(float* __restrict__ x, int nn) {
    int j = blockIdx.x * blockDim.x + threadIdx.x;
    if (j >= nn) return;
    float gp = 0.f, hp = 0.f, gr = 0.f, hr = 0.f;
    float v = x[j];
    for (int t = 0; t < T_STEPS; t++) {
        float vn = (t < T_STEPS - 1) ? x[(t + 1) * nn + j] : 0.f;  // prefetch
        hp = A_SR * (hp + gp);
        gp = fmaf(A_SR, gp, v);
        hr = A_RF * (hr + gr);
        gr = A_RF * gr;
        float u = fmaf(C_SR, hp, C_RF * hr);
        float s = (u >= THETA) ? 1.0f : 0.0f;
        x[t * nn + j] = s;
        gr += s;
        v = vn;
    }
}

// final psp: reads [t][44], writes d_out in (N,11,T) layout
__global__ void k_psp_final(const float* __restrict__ x, float* __restrict__ out) {
    int j = threadIdx.x;
    if (j >= 44) return;
    float gp = 0.f, hp = 0.f, gr = 0.f, hr = 0.f;
    for (int t = 0; t < T_STEPS; t++) {
        float v = x[t * 44 + j];
        hp = A_SR * (hp + gp);
        gp = fmaf(A_SR, gp, v);
        hr = A_RF * (hr + gr);
        gr = A_RF * gr;
        float u = fmaf(C_SR, hp, C_RF * hr);
        float s = (u >= THETA) ? 1.0f : 0.0f;
        out[j * T_STEPS + t] = s;
        gr += s;
    }
}

// ---------------- conv1: 5x5, 2->32, 32x32, pad 2 ----------------
// block 256 = 32(w) x 8(ty); each thread: 4 h-positions x 8 co
__global__ void k_conv1(const float* __restrict__ x, const float* __restrict__ w,
                        float* __restrict__ y) {
    __shared__ float in_s[2][36][36];   // padded slice
    __shared__ float w_s[400];          // 8 co x 2 ci x 25
    int m = blockIdx.x;      // t*4+n
    int cog = blockIdx.y;    // co base = cog*8
    int tid = threadIdx.x;
    for (int i = tid; i < 2 * 36 * 36; i += 256) ((float*)in_s)[i] = 0.f;
    __syncthreads();
    const float* xb = x + m * 2048;
    for (int i = tid; i < 2048; i += 256) {
        int ci = i >> 10, r = i & 1023, h = r >> 5, ww = r & 31;
        in_s[ci][h + 2][ww + 2] = xb[i];
    }
    for (int i = tid; i < 400; i += 256) w_s[i] = w[cog * 400 + i];
    __syncthreads();

    int wx = tid & 31, ty = tid >> 5;
    float acc[4][8];
#pragma unroll
    for (int p = 0; p < 4; p++)
#pragma unroll
        for (int j = 0; j < 8; j++) acc[p][j] = 0.f;

#pragma unroll
    for (int ci = 0; ci < 2; ci++)
#pragma unroll
        for (int kh = 0; kh < 5; kh++)
#pragma unroll
            for (int kw = 0; kw < 5; kw++) {
                float wv[8];
#pragma unroll
                for (int j = 0; j < 8; j++) wv[j] = w_s[j * 50 + ci * 25 + kh * 5 + kw];
                float v[4];
#pragma unroll
                for (int p = 0; p < 4; p++) v[p] = in_s[ci][ty + 8 * p + kh][wx + kw];
#pragma unroll
                for (int p = 0; p < 4; p++)
#pragma unroll
                    for (int j = 0; j < 8; j++) acc[p][j] = fmaf(v[p], wv[j], acc[p][j]);
            }

    float* yb = y + m * 32768 + cog * 8 * 1024;
#pragma unroll
    for (int p = 0; p < 4; p++) {
        int h = ty + 8 * p;
#pragma unroll
        for (int j = 0; j < 8; j++) yb[j * 1024 + h * 32 + wx] = acc[p][j];
    }
}

// ---------------- conv2: 3x3, 32->64, 16x16, pad 1 ----------------
// block 256 = 16(w) x 4(ty) x 4(g); thread: 4 h-positions x 8 co; grid.y=2 (co halves)
__global__ void k_conv2(const float* __restrict__ x, const float* __restrict__ w,
                        float* __restrict__ y) {
    extern __shared__ float sm[];
    float* in_s = sm;           // 32*18*18 = 10368
    float* w_s = sm + 10368;    // 32co * 32ci * 9 = 9216
    int m = blockIdx.x;
    int cog = blockIdx.y;
    int tid = threadIdx.x;
    for (int i = tid; i < 10368; i += 256) in_s[i] = 0.f;
    __syncthreads();
    const float* xb = x + m * 8192;
    for (int i = tid; i < 8192; i += 256) {
        int ci = i >> 8, r = i & 255, h = r >> 4, ww = r & 15;
        in_s[ci * 324 + (h + 1) * 18 + (ww + 1)] = xb[i];
    }
    const float* wb = w + cog * 32 * 288;
    for (int i = tid; i < 9216; i += 256) w_s[i] = wb[i];
    __syncthreads();

    int wx = tid & 15, ty = (tid >> 4) & 3, g = tid >> 6;
    float acc[4][8];
#pragma unroll
    for (int p = 0; p < 4; p++)
#pragma unroll
        for (int j = 0; j < 8; j++) acc[p][j] = 0.f;

    for (int ci = 0; ci < 32; ci++) {
        const float* ip = in_s + ci * 324 + wx;
        const float* wp = w_s + g * 8 * 288 + ci * 9;
#pragma unroll
        for (int kh = 0; kh < 3; kh++)
#pragma unroll
            for (int kw = 0; kw < 3; kw++) {
                float wv[8];
#pragma unroll
                for (int j = 0; j < 8; j++) wv[j] = wp[j * 288 + kh * 3 + kw];
                float v[4];
#pragma unroll
                for (int p = 0; p < 4; p++) v[p] = ip[(ty + 4 * p + kh) * 18 + kw];
#pragma unroll
                for (int p = 0; p < 4; p++)
#pragma unroll
                    for (int j = 0; j < 8; j++) acc[p][j] = fmaf(v[p], wv[j], acc[p][j]);
            }
    }

    float* yb = y + (m * 64 + cog * 32 + g * 8) * 256;
#pragma unroll
    for (int p = 0; p < 4; p++) {
        int h = ty + 4 * p;
#pragma unroll
        for (int j = 0; j < 8; j++) yb[j * 256 + h * 16 + wx] = acc[p][j];
    }
}

// ---------------- conv3: 3x3, 64->64, 8x8, pad 1 ----------------
// block 256 = 8(w) x 4(hy) x 8(g); thread: 2 h-positions x 8 co; all 64 co in one block
__global__ void k_conv3(const float* __restrict__ x, const float* __restrict__ w,
                        float* __restrict__ y) {
    extern __shared__ float sm[];
    float* in_s = sm;          // 64*10*10 = 6400
    float* w_s = sm + 6400;    // 64*64*9  = 36864
    int m = blockIdx.x;
    int tid = threadIdx.x;
    for (int i = tid; i < 6400; i += 256) in_s[i] = 0.f;
    __syncthreads();
    const float* xb = x + m * 4096;
    for (int i = tid; i < 4096; i += 256) {
        int ci = i >> 6, r = i & 63, h = r >> 3, ww = r & 7;
        in_s[ci * 100 + (h + 1) * 10 + (ww + 1)] = xb[i];
    }
    for (int i = tid; i < 36864; i += 256) w_s[i] = w[i];
    __syncthreads();

    int wx = tid & 7, hy = (tid >> 3) & 3, g = tid >> 5;
    float acc[2][8];
#pragma unroll
    for (int p = 0; p < 2; p++)
#pragma unroll
        for (int j = 0; j < 8; j++) acc[p][j] = 0.f;

    for (int ci = 0; ci < 64; ci++) {
        const float* ip = in_s + ci * 100 + wx;
        const float* wp = w_s + g * 8 * 576 + ci * 9;
#pragma unroll
        for (int kh = 0; kh < 3; kh++)
#pragma unroll
            for (int kw = 0; kw < 3; kw++) {
                float wv[8];
#pragma unroll
                for (int j = 0; j < 8; j++) wv[j] = wp[j * 576 + kh * 3 + kw];
                float v[2];
#pragma unroll
                for (int p = 0; p < 2; p++) v[p] = ip[(hy + 4 * p + kh) * 10 + kw];
#pragma unroll
                for (int p = 0; p < 2; p++)
#pragma unroll
                    for (int j = 0; j < 8; j++) acc[p][j] = fmaf(v[p], wv[j], acc[p][j]);
            }
    }

    float* yb = y + (m * 64 + g * 8) * 64;
#pragma unroll
    for (int p = 0; p < 2; p++) {
        int h = hy + 4 * p;
#pragma unroll
        for (int j = 0; j < 8; j++) yb[j * 64 + h * 8 + wx] = acc[p][j];
    }
}

// ---------------- fc1: C[1200][256] = X[1200][4096] . W[256][4096]^T ----------------
// tiled NT GEMM, BM=BN=64, BK=32, block 256, 4x4 microtile
__global__ void k_fc1(const float* __restrict__ X, const float* __restrict__ W,
                      float* __restrict__ C) {
    __shared__ float As[32][65];
    __shared__ float Bs[32][65];
    int bm = blockIdx.x, bn = blockIdx.y;
    int tid = threadIdx.x;
    int tx = tid & 15, ty = tid >> 4;
    int m0 = bm * 64, n0 = bn * 64;
    float acc[4][4];
#pragma unroll
    for (int i = 0; i < 4; i++)
#pragma unroll
        for (int j = 0; j < 4; j++) acc[i][j] = 0.f;

    for (int k0 = 0; k0 < 4096; k0 += 32) {
#pragma unroll
        for (int i = 0; i < 8; i++) {
            int idx = tid + i * 256;          // 0..2047 over 64x32 tile
            int l = idx >> 5, kk = idx & 31;
            int mg = m0 + l;
            As[kk][l] = (mg < MSL) ? X[mg * 4096 + k0 + kk] : 0.f;
            Bs[kk][l] = W[(n0 + l) * 4096 + k0 + kk];
        }
        __syncthreads();
#pragma unroll
        for (int kk = 0; kk < 32; kk++) {
            float a[4], b[4];
#pragma unroll
            for (int i = 0; i < 4; i++) a[i] = As[kk][ty * 4 + i];
#pragma unroll
            for (int j = 0; j < 4; j++) b[j] = Bs[kk][tx * 4 + j];
#pragma unroll
            for (int i = 0; i < 4; i++)
#pragma unroll
                for (int j = 0; j < 4; j++) acc[i][j] = fmaf(a[i], b[j], acc[i][j]);
        }
        __syncthreads();
    }
#pragma unroll
    for (int i = 0; i < 4; i++) {
        int mg = m0 + ty * 4 + i;
        if (mg < MSL) {
#pragma unroll
            for (int j = 0; j < 4; j++) C[mg * 256 + n0 + tx * 4 + j] = acc[i][j];
        }
    }
}

// ---------------- fc2: [1200][11] = [1200][256] . w4b[11][256]^T ----------------
__global__ void k_fc2(const float* __restrict__ x, const float* __restrict__ w,
                      float* __restrict__ y) {
    __shared__ float xs[256];
    int m = blockIdx.x;
    int tid = threadIdx.x;
    if (tid < 256) xs[tid] = x[m * 256 + tid];
    __syncthreads();
    int o = tid >> 5, lane = tid & 31;
    const float* wr = w + o * 256;
    float acc = 0.f;
#pragma unroll
    for (int i = 0; i < 8; i++) acc = fmaf(xs[lane + 32 * i], wr[lane + 32 * i], acc);
#pragma unroll
    for (int s = 16; s; s >>= 1) acc += __shfl_xor_sync(0xffffffffu, acc, s);
    if (lane == 0) y[m * 11 + o] = acc;
}

// ---------------- host ----------------
extern "C" void kernel_launch(void* const* d_in, const int* in_sizes, int n_in,
                              void* d_out, int out_size) {
    const float* s_in = (const float*)d_in[0];
    const float* w1 = (const float*)d_in[1];
    const float* w2 = (const float*)d_in[2];
    const float* w3 = (const float*)d_in[3];
    const float* w4a = (const float*)d_in[4];
    const float* w4b = (const float*)d_in[5];
    float* out = (float*)d_out;

    float *b1, *b2, *b3, *b4, *b5, *b6, *b7, *b8;
    cudaGetSymbolAddress((void**)&b1, g_buf1);
    cudaGetSymbolAddress((void**)&b2, g_buf2);
    cudaGetSymbolAddress((void**)&b3, g_buf3);
    cudaGetSymbolAddress((void**)&b4, g_buf4);
    cudaGetSymbolAddress((void**)&b5, g_buf5);
    cudaGetSymbolAddress((void**)&b6, g_buf6);
    cudaGetSymbolAddress((void**)&b7, g_buf7);
    cudaGetSymbolAddress((void**)&b8, g_buf8);

    cudaFuncSetAttribute(k_conv2, cudaFuncAttributeMaxDynamicSharedMemorySize, 78336);
    cudaFuncSetAttribute(k_conv3, cudaFuncAttributeMaxDynamicSharedMemorySize, 173056);

    k_pool4<<<(2457600 + 255) / 256, 256>>>(s_in, b1);
    k_psp<<<8192 / 256, 256>>>(b1, 8192);

    k_conv1<<<dim3(MSL, 4), 256>>>(b1, w1, b2);
    k_psp<<<131072 / 256, 256>>>(b2, 131072);

    k_pool2<<<(9830400 + 255) / 256, 256>>>(b2, b3, 32, 16, 16, 9830400);
    k_psp<<<32768 / 256, 256>>>(b3, 32768);

    k_conv2<<<dim3(MSL, 2), 256, 78336>>>(b3, w2, b4);
    k_psp<<<65536 / 256, 256>>>(b4, 65536);

    k_pool2<<<(4915200 + 255) / 256, 256>>>(b4, b5, 64, 8, 8, 4915200);
    k_psp<<<16384 / 256, 256>>>(b5, 16384);

    k_conv3<<<MSL, 256, 173056>>>(b5, w3, b6);
    k_psp<<<16384 / 256, 256>>>(b6, 16384);

    k_fc1<<<dim3(19, 4), 256>>>(b6, w4a, b7);
    k_psp<<<1024 / 256, 256>>>(b7, 1024);

    k_fc2<<<MSL, 352>>>(b7, w4b, b8);
    k_psp_final<<<1, 64>>>(b8, out);
}